// round 6
// baseline (speedup 1.0000x reference)
#include <cuda_runtime.h>
#include <cuda_fp16.h>
#include <cstdint>

// ---------------- constants ----------------
#define GRID_CTAS 148
#define THREADS   512                   // 15 consumer warps + 1 producer warp
#define TILE_M    224                   // 14 slots of 16 rows
#define NROWS     1048576
#define NTILES    4682                  // ceil(NROWS/224); last tile = 32 rows

// smem byte offsets (from 1024-aligned dynamic base)
#define SM_B1CAT  0                     // 256 f32 layer-1 biases (b|c)
#define SM_B2S    1024                  // 128 f32 layer-2 biases (b|c)
#define SM_CNTS   1536                  // [0]=cb0 [1]=cc0 [2]=cb1 [3]=cc1
#define SM_ROWPOS 1600                  // 224 int (producer-private, single buf)
#define SM_PERM0  2496                  // 224 int
#define SM_PERM1  3392                  // 224 int
#define SM_B1     4352                  // W1cat fp16 [k=64][n=256] ld=264 -> 33792 B
#define SM_B2     38144                 // W2cat fp16 [k=256][n=64] ld=72  -> 36864 B
#define SM_A1_0   75008                 // permuted tile fp16 [224][72]    -> 32256 B
#define SM_A1_1   107264                // second buffer                   -> 32256 B
#define SMEM_BYTES (139520 + 1024)

#define LD1 264   // halfs per row of B1
#define LD2 72    // halfs per row of B2
#define LDA 72    // halfs per row of A1
#define A1ROW 144 // bytes per row of A1

// named barrier ids: full[buf] = 1+buf, free[buf] = 3+buf
#define BAR_SYNC(id)   asm volatile("bar.sync %0, %1;"   :: "r"(id), "r"(512) : "memory")
#define BAR_ARRIVE(id) asm volatile("bar.arrive %0, %1;" :: "r"(id), "r"(512) : "memory")
#define MEMBAR_CTA()   asm volatile("membar.cta;" ::: "memory")

// ---------------- ptx helpers ----------------
__device__ __forceinline__ uint32_t s2u(const void* p) {
    uint32_t a;
    asm("{ .reg .u64 t; cvta.to.shared.u64 t, %1; cvt.u32.u64 %0, t; }" : "=r"(a) : "l"(p));
    return a;
}
__device__ __forceinline__ void ldsm_x4(uint32_t* r, uint32_t addr) {
    asm volatile("ldmatrix.sync.aligned.m8n8.x4.shared.b16 {%0,%1,%2,%3}, [%4];"
                 : "=r"(r[0]), "=r"(r[1]), "=r"(r[2]), "=r"(r[3]) : "r"(addr));
}
__device__ __forceinline__ void ldsm_x4t(uint32_t* r, uint32_t addr) {
    asm volatile("ldmatrix.sync.aligned.m8n8.x4.trans.shared.b16 {%0,%1,%2,%3}, [%4];"
                 : "=r"(r[0]), "=r"(r[1]), "=r"(r[2]), "=r"(r[3]) : "r"(addr));
}
__device__ __forceinline__ void mma16816(float* d, const uint32_t* a, uint32_t b0, uint32_t b1) {
    asm volatile("mma.sync.aligned.m16n8k16.row.col.f32.f16.f16.f32 "
                 "{%0,%1,%2,%3}, {%4,%5,%6,%7}, {%8,%9}, {%0,%1,%2,%3};"
                 : "+f"(d[0]), "+f"(d[1]), "+f"(d[2]), "+f"(d[3])
                 : "r"(a[0]), "r"(a[1]), "r"(a[2]), "r"(a[3]), "r"(b0), "r"(b1));
}
__device__ __forceinline__ uint32_t packh2(float x, float y) {
    __half2 h = __floats2half2_rn(x, y);
    return *reinterpret_cast<uint32_t*>(&h);
}

// ---------------- kernel ----------------
extern "C" __global__ void __launch_bounds__(THREADS, 1)
STAR_moe_mlp_kernel(
    const float* __restrict__ obs,
    const float* __restrict__ W1b, const float* __restrict__ b1b,
    const float* __restrict__ W2b, const float* __restrict__ b2b,
    const float* __restrict__ W1c, const float* __restrict__ b1c,
    const float* __restrict__ W2c, const float* __restrict__ b2c,
    const float* __restrict__ W1p, const float* __restrict__ b1p,
    const float* __restrict__ W2p, const float* __restrict__ b2p,
    float* __restrict__ out)
{
    extern __shared__ char smem_raw[];
    uint32_t sb0 = s2u(smem_raw);
    uint32_t sb  = (sb0 + 1023u) & ~1023u;
    char* smb = smem_raw + (sb - sb0);

    const int tid = threadIdx.x;
    const int wid = tid >> 5, l = tid & 31;

    float* b1cat  = reinterpret_cast<float*>(smb + SM_B1CAT);
    float* b2s    = reinterpret_cast<float*>(smb + SM_B2S);
    int*   cnts   = reinterpret_cast<int*>(smb + SM_CNTS);
    int*   rowpos = reinterpret_cast<int*>(smb + SM_ROWPOS);

    // ---- one-time setup: fused weights (fp16) + biases into SMEM ----
    for (int idx = tid; idx < 64 * 256; idx += THREADS) {       // B1: [k=64][n=256] (b|c)
        int k = idx >> 8, n = idx & 255;
        float w = (n < 128) ? W1b[k * 128 + n] * W1p[k * 128 + n]
                            : W1c[k * 128 + (n - 128)] * W1p[k * 128 + (n - 128)];
        *reinterpret_cast<__half*>(smb + SM_B1 + (uint32_t)(k * LD1 + n) * 2) = __float2half_rn(w);
    }
    for (int idx = tid; idx < 256 * 64; idx += THREADS) {       // B2: [k=256][n=64] (b|c in k)
        int k = idx >> 6, n = idx & 63;
        float w = (k < 128) ? W2b[k * 64 + n] * W2p[k * 64 + n]
                            : W2c[(k - 128) * 64 + n] * W2p[(k - 128) * 64 + n];
        *reinterpret_cast<__half*>(smb + SM_B2 + (uint32_t)(k * LD2 + n) * 2) = __float2half_rn(w);
    }
    for (int i = tid; i < 256; i += THREADS)
        b1cat[i] = (i < 128) ? b1b[i] + b1p[i] : b1c[i - 128] + b1p[i - 128];
    for (int i = tid; i < 128; i += THREADS)
        b2s[i] = (i < 64) ? b2b[i] + b2p[i] : b2c[i - 64] + b2p[i - 64];
    __syncthreads();   // last block-wide sync; only named barriers below

    if (wid == 15) {
        // ================= PRODUCER WARP =================
        for (int it = 0;; it++) {
            int tile = blockIdx.x + it * GRID_CTAS;
            if (tile >= NTILES) break;
            const int bufi = it & 1;
            if (it >= 2) BAR_SYNC(3 + bufi);          // wait buffer free

            int*     perm = reinterpret_cast<int*>(smb + (bufi ? SM_PERM1 : SM_PERM0));
            char*    a1   = smb + (bufi ? SM_A1_1 : SM_A1_0);
            int*     cb   = cnts + bufi * 2;
            size_t   rb   = (size_t)tile * TILE_M;

            // init perm + counters
            #pragma unroll
            for (int p = l; p < TILE_M; p += 32) perm[p] = -1;
            if (l == 0) { cb[0] = 0; cb[1] = 0; }
            __syncwarp();

            // flag pass: read routing cols, build perm/rowpos
            for (int r = l; r < TILE_M; r += 32) {
                if (rb + (size_t)r < (size_t)NROWS) {
                    float2 fl = *reinterpret_cast<const float2*>(obs + (rb + r) * 64 + 2);
                    bool isb = (fl.x == 1.0f && fl.y == 0.0f);
                    int pos = isb ? atomicAdd(&cb[0], 1)
                                  : (TILE_M - 1) - atomicAdd(&cb[1], 1);
                    perm[pos] = (r << 1) | (isb ? 1 : 0);
                    rowpos[r] = pos;
                }
            }
            __syncwarp();

            // data pass: coalesced LDG fp32 -> fp16 -> STS permuted
            const float4* g = reinterpret_cast<const float4*>(obs + rb * 64);
            #pragma unroll 4
            for (int i = 0; i < TILE_M * 16 / 32; i++) {
                int f = l + 32 * i;
                int row = f >> 4, c4 = f & 15;
                if (rb + (size_t)row < (size_t)NROWS) {
                    int pos = rowpos[row];
                    float4 x = g[f];
                    uint2 pp;
                    pp.x = packh2(x.x, x.y);
                    pp.y = packh2(x.z, x.w);
                    *reinterpret_cast<uint2*>(a1 + (uint32_t)(pos * A1ROW + c4 * 8)) = pp;
                }
            }
            MEMBAR_CTA();
            BAR_ARRIVE(1 + bufi);                     // publish buffer full
        }
    } else {
        // ================= CONSUMER WARPS (0-14) =================
        for (int it = 0;; it++) {
            int tile = blockIdx.x + it * GRID_CTAS;
            if (tile >= NTILES) break;
            const int bufi = it & 1;
            BAR_SYNC(1 + bufi);                       // wait buffer full

            int*     perm = reinterpret_cast<int*>(smb + (bufi ? SM_PERM1 : SM_PERM0));
            uint32_t a1b  = sb + (bufi ? SM_A1_1 : SM_A1_0);

            int cnt_b = cnts[bufi * 2], cnt_c = cnts[bufi * 2 + 1];
            int cstart = TILE_M - cnt_c;
            int sb_slots = (cnt_b + 15) >> 4;
            int slot, e;
            bool active;
            if (wid < sb_slots) { slot = wid; e = 1; active = true; }
            else { slot = (cstart >> 4) + (wid - sb_slots); e = 0; active = (slot <= 13); }

            if (active) {
                // expert half: b (e=1) at hidden cols [0,128), c (e=0) at [128,256)
                const int ebase = e ? 0 : 128;

                uint32_t a1f[4][4];
                #pragma unroll
                for (int kb = 0; kb < 4; kb++)
                    ldsm_x4(a1f[kb], a1b + (uint32_t)((slot * 16 + (l & 15)) * LDA
                                                      + kb * 16 + (l >> 4) * 8) * 2);

                float acc2[8][4];
                #pragma unroll
                for (int nbt = 0; nbt < 8; nbt++)
                    #pragma unroll
                    for (int q = 0; q < 4; q++) acc2[nbt][q] = 0.f;

                #pragma unroll
                for (int c = 0; c < 2; c++) {
                    int hbase = ebase + c * 64;
                    float acc1[8][4];
                    #pragma unroll
                    for (int nbt = 0; nbt < 8; nbt++)
                        #pragma unroll
                        for (int q = 0; q < 4; q++) acc1[nbt][q] = 0.f;

                    #pragma unroll
                    for (int p = 0; p < 4; p++)
                        #pragma unroll
                        for (int kb = 0; kb < 4; kb++) {
                            uint32_t b[4];
                            ldsm_x4t(b, sb + SM_B1 + (uint32_t)((kb * 16 + (l & 15)) * LD1
                                                                + hbase + p * 16 + (l >> 4) * 8) * 2);
                            mma16816(acc1[2 * p],     a1f[kb], b[0], b[1]);
                            mma16816(acc1[2 * p + 1], a1f[kb], b[2], b[3]);
                        }

                    uint32_t a2[4][4];
                    #pragma unroll
                    for (int nbt = 0; nbt < 8; nbt++) {
                        int colb = hbase + nbt * 8 + 2 * (l & 3);
                        float2 bi = *reinterpret_cast<const float2*>(b1cat + colb);
                        float v0 = fmaxf(acc1[nbt][0] + bi.x, 0.f);
                        float v1 = fmaxf(acc1[nbt][1] + bi.y, 0.f);
                        float v2 = fmaxf(acc1[nbt][2] + bi.x, 0.f);
                        float v3 = fmaxf(acc1[nbt][3] + bi.y, 0.f);
                        a2[nbt >> 1][(nbt & 1) * 2 + 0] = packh2(v0, v1);
                        a2[nbt >> 1][(nbt & 1) * 2 + 1] = packh2(v2, v3);
                    }

                    #pragma unroll
                    for (int p2 = 0; p2 < 4; p2++)
                        #pragma unroll
                        for (int kb = 0; kb < 4; kb++) {
                            uint32_t b[4];
                            ldsm_x4t(b, sb + SM_B2 + (uint32_t)((hbase + kb * 16 + (l & 15)) * LD2
                                                                + p2 * 16 + (l >> 4) * 8) * 2);
                            mma16816(acc2[2 * p2],     a2[kb], b[0], b[1]);
                            mma16816(acc2[2 * p2 + 1], a2[kb], b[2], b[3]);
                        }
                }

                // store: routed bias, scatter by perm, gate overlap/invalid rows
                const float* bb = b2s + (e ? 0 : 64);
                int p0 = slot * 16 + (l >> 2), p1 = p0 + 8;
                int v0 = perm[p0], v1 = perm[p1];
                bool s0 = (v0 >= 0) && ((v0 & 1) == e);
                bool s1 = (v1 >= 0) && ((v1 & 1) == e);
                size_t base = (size_t)tile * TILE_M;
                float* o0 = out + (base + (size_t)(v0 >> 1)) * 64;
                float* o1 = out + (base + (size_t)(v1 >> 1)) * 64;
                #pragma unroll
                for (int nbt = 0; nbt < 8; nbt++) {
                    int cb2 = nbt * 8 + (l & 3) * 2;
                    if (s0) {
                        float2 o; o.x = acc2[nbt][0] + bb[cb2]; o.y = acc2[nbt][1] + bb[cb2 + 1];
                        *reinterpret_cast<float2*>(o0 + cb2) = o;
                    }
                    if (s1) {
                        float2 o; o.x = acc2[nbt][2] + bb[cb2]; o.y = acc2[nbt][3] + bb[cb2 + 1];
                        *reinterpret_cast<float2*>(o1 + cb2) = o;
                    }
                }
            }
            BAR_ARRIVE(3 + bufi);                     // release buffer
        }
    }
}

// ---------------- launch ----------------
extern "C" void kernel_launch(void* const* d_in, const int* in_sizes, int n_in,
                              void* d_out, int out_size) {
    (void)in_sizes; (void)n_in; (void)out_size;
    cudaFuncSetAttribute(STAR_moe_mlp_kernel,
                         cudaFuncAttributeMaxDynamicSharedMemorySize, SMEM_BYTES);
    STAR_moe_mlp_kernel<<<GRID_CTAS, THREADS, SMEM_BYTES>>>(
        (const float*)d_in[0],
        (const float*)d_in[1],  (const float*)d_in[2],
        (const float*)d_in[3],  (const float*)d_in[4],
        (const float*)d_in[5],  (const float*)d_in[6],
        (const float*)d_in[7],  (const float*)d_in[8],
        (const float*)d_in[9],  (const float*)d_in[10],
        (const float*)d_in[11], (const float*)d_in[12],
        (float*)d_out);
}

// round 8
// speedup vs baseline: 6.2663x; 6.2663x over previous
#include <cuda_runtime.h>
#include <cuda_fp16.h>
#include <cstdint>

// ---------------- constants ----------------
#define GRID_CTAS 148
#define THREADS   384                   // 12 warps; 11 slots of 32 rows + overlap warp
#define TILE_M    352
#define NROWS     1048576
#define NTILES    2979                  // ceil(NROWS/352); last tile = 320 valid rows
#define TILE_F4   5632                  // TILE_M*16 float4s per tile
#define NF4       16777216              // NROWS*16

// smem byte offsets (from 1024-aligned dynamic base)
#define SM_B1CAT  0                     // 256 f32 layer-1 biases (b|c)
#define SM_B2S    1024                  // 128 f32 layer-2 biases (b|c)
#define SM_CNT    1536                  // 2 int counters
#define SM_PERM   1600                  // 352 int: pos -> (row<<1)|isb, -1 invalid
#define SM_B1     3072                  // W1cat fp16 [k=64][n=256] ld=264 -> 33792 B
#define SM_B2     36864                 // W2cat fp16 [k=256][n=64] ld=72  -> 36864 B
#define SM_A1     73728                 // permuted tile fp16 [352][72]    -> 50688 B
#define SM_XS     124416                // obs tile fp32 staging [352][64] -> 90112 B
#define SMEM_BYTES (214528 + 1024)

#define LD1 264   // halfs per row of B1
#define LD2 72    // halfs per row of B2
#define LDA 72    // halfs per row of A1

// ---------------- ptx helpers ----------------
__device__ __forceinline__ uint32_t s2u(const void* p) {
    uint32_t a;
    asm("{ .reg .u64 t; cvta.to.shared.u64 t, %1; cvt.u32.u64 %0, t; }" : "=r"(a) : "l"(p));
    return a;
}
__device__ __forceinline__ void ldsm_x4(uint32_t* r, uint32_t addr) {
    asm volatile("ldmatrix.sync.aligned.m8n8.x4.shared.b16 {%0,%1,%2,%3}, [%4];"
                 : "=r"(r[0]), "=r"(r[1]), "=r"(r[2]), "=r"(r[3]) : "r"(addr));
}
__device__ __forceinline__ void ldsm_x4t(uint32_t* r, uint32_t addr) {
    asm volatile("ldmatrix.sync.aligned.m8n8.x4.trans.shared.b16 {%0,%1,%2,%3}, [%4];"
                 : "=r"(r[0]), "=r"(r[1]), "=r"(r[2]), "=r"(r[3]) : "r"(addr));
}
__device__ __forceinline__ void mma16816(float* d, const uint32_t* a, uint32_t b0, uint32_t b1) {
    asm volatile("mma.sync.aligned.m16n8k16.row.col.f32.f16.f16.f32 "
                 "{%0,%1,%2,%3}, {%4,%5,%6,%7}, {%8,%9}, {%0,%1,%2,%3};"
                 : "+f"(d[0]), "+f"(d[1]), "+f"(d[2]), "+f"(d[3])
                 : "r"(a[0]), "r"(a[1]), "r"(a[2]), "r"(a[3]), "r"(b0), "r"(b1));
}
__device__ __forceinline__ void cp16(uint32_t dst, const void* src) {
    asm volatile("cp.async.cg.shared.global [%0], [%1], 16;" :: "r"(dst), "l"(src));
}
#define CP_COMMIT() asm volatile("cp.async.commit_group;" ::: "memory")
#define CP_WAIT0()  asm volatile("cp.async.wait_group 0;" ::: "memory")

__device__ __forceinline__ uint32_t packh2(float x, float y) {
    __half2 h = __floats2half2_rn(x, y);
    return *reinterpret_cast<uint32_t*>(&h);
}

// ---------------- kernel ----------------
extern "C" __global__ void __launch_bounds__(THREADS, 1)
STAR_moe_mlp_kernel(
    const float* __restrict__ obs,
    const float* __restrict__ W1b, const float* __restrict__ b1b,
    const float* __restrict__ W2b, const float* __restrict__ b2b,
    const float* __restrict__ W1c, const float* __restrict__ b1c,
    const float* __restrict__ W2c, const float* __restrict__ b2c,
    const float* __restrict__ W1p, const float* __restrict__ b1p,
    const float* __restrict__ W2p, const float* __restrict__ b2p,
    float* __restrict__ out)
{
    extern __shared__ char smem_raw[];
    uint32_t sb0 = s2u(smem_raw);
    uint32_t sb  = (sb0 + 1023u) & ~1023u;
    char* smb = smem_raw + (sb - sb0);

    const int tid = threadIdx.x;
    const int wid = tid >> 5, l = tid & 31;

    int*   perm  = reinterpret_cast<int*>(smb + SM_PERM);
    int*   cnts  = reinterpret_cast<int*>(smb + SM_CNT);
    float* b1cat = reinterpret_cast<float*>(smb + SM_B1CAT);
    float* b2s   = reinterpret_cast<float*>(smb + SM_B2S);

    // ---- one-time setup: fused weights (fp16) + biases into SMEM ----
    for (int idx = tid; idx < 64 * 256; idx += THREADS) {       // B1: [k=64][n=256] (b|c)
        int k = idx >> 8, n = idx & 255;
        float w = (n < 128) ? W1b[k * 128 + n] * W1p[k * 128 + n]
                            : W1c[k * 128 + (n - 128)] * W1p[k * 128 + (n - 128)];
        *reinterpret_cast<__half*>(smb + SM_B1 + (uint32_t)(k * LD1 + n) * 2) = __float2half_rn(w);
    }
    for (int idx = tid; idx < 256 * 64; idx += THREADS) {       // B2: [k=256][n=64] (b|c in k)
        int k = idx >> 6, n = idx & 63;
        float w = (k < 128) ? W2b[k * 64 + n] * W2p[k * 64 + n]
                            : W2c[(k - 128) * 64 + n] * W2p[(k - 128) * 64 + n];
        *reinterpret_cast<__half*>(smb + SM_B2 + (uint32_t)(k * LD2 + n) * 2) = __float2half_rn(w);
    }
    for (int i = tid; i < 256; i += THREADS)
        b1cat[i] = (i < 128) ? b1b[i] + b1p[i] : b1c[i - 128] + b1p[i - 128];
    for (int i = tid; i < 128; i += THREADS)
        b2s[i] = (i < 64) ? b2b[i] + b2p[i] : b2c[i - 64] + b2p[i - 64];

    // ---- prologue: async-load first obs tile (tiles < 148 are fully valid) ----
    {
        const float4* g = reinterpret_cast<const float4*>(obs + (size_t)blockIdx.x * (TILE_M * 64));
        #pragma unroll
        for (int i = 0; i < 15; i++) {
            int f = i * THREADS + tid;
            if (f < TILE_F4) cp16(sb + SM_XS + (uint32_t)f * 16, g + f);
        }
    }
    CP_COMMIT();

    for (int it = 0;; it++) {
        int tile = blockIdx.x + it * GRID_CTAS;
        if (tile >= NTILES) break;

        CP_WAIT0();
        __syncthreads();                       // staging ready; prev-tile A1 reads done

        // ---- init permutation state ----
        if (tid < TILE_M) perm[tid] = -1;
        if (tid == 0) { cnts[0] = 0; cnts[1] = 0; }
        __syncthreads();

        // ---- mask + permutation pass: b-rows pack low, c-rows pack high ----
        if (tid < TILE_M) {
            if (tile * TILE_M + tid < NROWS) {
                float2 v = *reinterpret_cast<const float2*>(smb + SM_XS + tid * 256 + 8);
                bool isb = (v.x == 1.0f && v.y == 0.0f);
                int pos = isb ? atomicAdd(&cnts[0], 1)
                              : (TILE_M - 1) - atomicAdd(&cnts[1], 1);
                perm[pos] = (tid << 1) | (isb ? 1 : 0);
            }
        }
        __syncthreads();

        // ---- convert pass: gather fp32 rows by position -> fp16 A1 (permuted) ----
        {
            const float4* xs4 = reinterpret_cast<const float4*>(smb + SM_XS);
            #pragma unroll
            for (int i = 0; i < 15; i++) {
                int f = i * THREADS + tid;
                if (f < TILE_F4) {
                    int p = f >> 4, c4 = f & 15;
                    int v = perm[p];
                    if (v >= 0) {
                        float4 x = xs4[(v >> 1) * 16 + c4];
                        uint2 pp;
                        pp.x = packh2(x.x, x.y);
                        pp.y = packh2(x.z, x.w);
                        *reinterpret_cast<uint2*>(smb + SM_A1 + (uint32_t)(p * (LDA * 2) + c4 * 8)) = pp;
                    }
                }
            }
        }
        __syncthreads();

        // ---- prefetch next tile (guarded; overlaps compute) ----
        int nt = tile + GRID_CTAS;
        if (nt < NTILES) {
            const float4* g = reinterpret_cast<const float4*>(obs + (size_t)nt * (TILE_M * 64));
            int lim = NF4 - nt * TILE_F4;
            if (lim > TILE_F4) lim = TILE_F4;
            #pragma unroll
            for (int i = 0; i < 15; i++) {
                int f = i * THREADS + tid;
                if (f < lim) cp16(sb + SM_XS + (uint32_t)f * 16, g + f);
            }
        }
        CP_COMMIT();

        // ---- slot assignment: one 32-row single-expert slot per warp ----
        int cnt_b = cnts[0], cnt_c = cnts[1];
        int cstart = TILE_M - cnt_c;
        int sb_slots = (cnt_b + 31) >> 5;
        int slot, e;
        bool active;
        if (wid < sb_slots) { slot = wid; e = 1; active = true; }
        else { slot = (cstart >> 5) + (wid - sb_slots); e = 0; active = (slot <= 10); }

        if (active) {
            // expert half: b (e=1) at hidden cols [0,128), c (e=0) at [128,256)
            const int ebase = e ? 0 : 128;

            // A fragments: 2 halves of 16 rows x k64
            uint32_t a1f[2][4][4];
            #pragma unroll
            for (int h = 0; h < 2; h++)
                #pragma unroll
                for (int kb = 0; kb < 4; kb++)
                    ldsm_x4(a1f[h][kb],
                            sb + SM_A1 + (uint32_t)((slot * 32 + h * 16 + (l & 15)) * LDA
                                                    + kb * 16 + (l >> 4) * 8) * 2);

            float acc2[2][8][4];
            #pragma unroll
            for (int h = 0; h < 2; h++)
                #pragma unroll
                for (int nbt = 0; nbt < 8; nbt++)
                    #pragma unroll
                    for (int q = 0; q < 4; q++) acc2[h][nbt][q] = 0.f;

            // ---- interleaved: per n16 hidden group: L1 mma -> relu -> L2 mma ----
            #pragma unroll
            for (int c = 0; c < 2; c++) {
                int hbase = ebase + c * 64;
                #pragma unroll
                for (int p = 0; p < 4; p++) {
                    float acc1[2][2][4];
                    #pragma unroll
                    for (int h = 0; h < 2; h++)
                        #pragma unroll
                        for (int j = 0; j < 2; j++)
                            #pragma unroll
                            for (int q = 0; q < 4; q++) acc1[h][j][q] = 0.f;

                    #pragma unroll
                    for (int kb = 0; kb < 4; kb++) {
                        uint32_t b[4];
                        ldsm_x4t(b, sb + SM_B1 + (uint32_t)((kb * 16 + (l & 15)) * LD1
                                                            + hbase + p * 16 + (l >> 4) * 8) * 2);
                        #pragma unroll
                        for (int h = 0; h < 2; h++) {
                            mma16816(acc1[h][0], a1f[h][kb], b[0], b[1]);
                            mma16816(acc1[h][1], a1f[h][kb], b[2], b[3]);
                        }
                    }

                    // bias + relu -> fp16 L2-A fragment for this k16 group
                    uint32_t a2[2][4];
                    #pragma unroll
                    for (int h = 0; h < 2; h++)
                        #pragma unroll
                        for (int j = 0; j < 2; j++) {
                            int colb = hbase + p * 16 + j * 8 + 2 * (l & 3);
                            float2 bi = *reinterpret_cast<const float2*>(b1cat + colb);
                            float v0 = fmaxf(acc1[h][j][0] + bi.x, 0.f);
                            float v1 = fmaxf(acc1[h][j][1] + bi.y, 0.f);
                            float v2 = fmaxf(acc1[h][j][2] + bi.x, 0.f);
                            float v3 = fmaxf(acc1[h][j][3] + bi.y, 0.f);
                            a2[h][j * 2 + 0] = packh2(v0, v1);
                            a2[h][j * 2 + 1] = packh2(v2, v3);
                        }

                    // L2 partial accumulation for this k16 group
                    #pragma unroll
                    for (int p2 = 0; p2 < 4; p2++) {
                        uint32_t b[4];
                        ldsm_x4t(b, sb + SM_B2 + (uint32_t)((hbase + p * 16 + (l & 15)) * LD2
                                                            + p2 * 16 + (l >> 4) * 8) * 2);
                        #pragma unroll
                        for (int h = 0; h < 2; h++) {
                            mma16816(acc2[h][2 * p2],     a2[h], b[0], b[1]);
                            mma16816(acc2[h][2 * p2 + 1], a2[h], b[2], b[3]);
                        }
                    }
                }
            }

            // ---- store: routed bias, scatter by perm, gate overlap/invalid rows ----
            const float* bb = b2s + (e ? 0 : 64);
            size_t base = (size_t)tile * TILE_M;
            #pragma unroll
            for (int h = 0; h < 2; h++) {
                int p0 = slot * 32 + h * 16 + (l >> 2), p1 = p0 + 8;
                int v0 = perm[p0], v1 = perm[p1];
                bool s0 = (v0 >= 0) && ((v0 & 1) == e);
                bool s1 = (v1 >= 0) && ((v1 & 1) == e);
                float* o0 = out + (base + (size_t)(v0 >> 1)) * 64;
                float* o1 = out + (base + (size_t)(v1 >> 1)) * 64;
                #pragma unroll
                for (int nbt = 0; nbt < 8; nbt++) {
                    int cb2 = nbt * 8 + (l & 3) * 2;
                    if (s0) {
                        float2 o; o.x = acc2[h][nbt][0] + bb[cb2]; o.y = acc2[h][nbt][1] + bb[cb2 + 1];
                        *reinterpret_cast<float2*>(o0 + cb2) = o;
                    }
                    if (s1) {
                        float2 o; o.x = acc2[h][nbt][2] + bb[cb2]; o.y = acc2[h][nbt][3] + bb[cb2 + 1];
                        *reinterpret_cast<float2*>(o1 + cb2) = o;
                    }
                }
            }
        }
    }
}

// ---------------- launch ----------------
extern "C" void kernel_launch(void* const* d_in, const int* in_sizes, int n_in,
                              void* d_out, int out_size) {
    (void)in_sizes; (void)n_in; (void)out_size;
    cudaFuncSetAttribute(STAR_moe_mlp_kernel,
                         cudaFuncAttributeMaxDynamicSharedMemorySize, SMEM_BYTES);
    STAR_moe_mlp_kernel<<<GRID_CTAS, THREADS, SMEM_BYTES>>>(
        (const float*)d_in[0],
        (const float*)d_in[1],  (const float*)d_in[2],
        (const float*)d_in[3],  (const float*)d_in[4],
        (const float*)d_in[5],  (const float*)d_in[6],
        (const float*)d_in[7],  (const float*)d_in[8],
        (const float*)d_in[9],  (const float*)d_in[10],
        (const float*)d_in[11], (const float*)d_in[12],
        (float*)d_out);
}

// round 9
// speedup vs baseline: 6.7235x; 1.0730x over previous
#include <cuda_runtime.h>
#include <cuda_fp16.h>
#include <cstdint>

// ---------------- constants ----------------
#define GRID_CTAS 148
#define THREADS   640                   // 20 warps; 19 slots of 16 rows + overlap
#define TILE_M    304
#define NROWS     1048576
#define NTILES    3450                  // ceil(NROWS/304); last tile = 80 valid rows
#define TILE_F4   4864                  // TILE_M*16 float4s per tile
#define NF4       16777216              // NROWS*16

// smem byte offsets (from 1024-aligned dynamic base)
#define SM_B1CAT  0                     // 256 f32 layer-1 biases (b|c)
#define SM_B2S    1024                  // 128 f32 layer-2 biases (b|c)
#define SM_CNT    1536                  // 4 int counters (parity pairs)
#define SM_PERM   1600                  // 304 int: pos -> (row<<1)|isb, -1 invalid
#define SM_B1     3072                  // W1cat fp16 [k=64][n=256] ld=264 -> 33792 B
#define SM_B2     36864                 // W2cat fp16 [k=256][n=64] ld=72  -> 36864 B
#define SM_A1     73728                 // obs tile fp16 [304][72] UNPERMUTED -> 43776 B
#define SM_XS     117504                // obs tile fp32 staging [304][64]   -> 77824 B
#define SMEM_BYTES (195328 + 1024)

#define LD1 264   // halfs per row of B1
#define LD2 72    // halfs per row of B2
#define LDA 72    // halfs per row of A1 (144 B)

// ---------------- ptx helpers ----------------
__device__ __forceinline__ uint32_t s2u(const void* p) {
    uint32_t a;
    asm("{ .reg .u64 t; cvta.to.shared.u64 t, %1; cvt.u32.u64 %0, t; }" : "=r"(a) : "l"(p));
    return a;
}
__device__ __forceinline__ void ldsm_x4(uint32_t* r, uint32_t addr) {
    asm volatile("ldmatrix.sync.aligned.m8n8.x4.shared.b16 {%0,%1,%2,%3}, [%4];"
                 : "=r"(r[0]), "=r"(r[1]), "=r"(r[2]), "=r"(r[3]) : "r"(addr));
}
__device__ __forceinline__ void ldsm_x4t(uint32_t* r, uint32_t addr) {
    asm volatile("ldmatrix.sync.aligned.m8n8.x4.trans.shared.b16 {%0,%1,%2,%3}, [%4];"
                 : "=r"(r[0]), "=r"(r[1]), "=r"(r[2]), "=r"(r[3]) : "r"(addr));
}
__device__ __forceinline__ void mma16816(float* d, const uint32_t* a, uint32_t b0, uint32_t b1) {
    asm volatile("mma.sync.aligned.m16n8k16.row.col.f32.f16.f16.f32 "
                 "{%0,%1,%2,%3}, {%4,%5,%6,%7}, {%8,%9}, {%0,%1,%2,%3};"
                 : "+f"(d[0]), "+f"(d[1]), "+f"(d[2]), "+f"(d[3])
                 : "r"(a[0]), "r"(a[1]), "r"(a[2]), "r"(a[3]), "r"(b0), "r"(b1));
}
__device__ __forceinline__ void cp16(uint32_t dst, const void* src) {
    asm volatile("cp.async.cg.shared.global [%0], [%1], 16;" :: "r"(dst), "l"(src));
}
#define CP_COMMIT() asm volatile("cp.async.commit_group;" ::: "memory")
#define CP_WAIT0()  asm volatile("cp.async.wait_group 0;" ::: "memory")

__device__ __forceinline__ uint32_t packh2(float x, float y) {
    __half2 h = __floats2half2_rn(x, y);
    return *reinterpret_cast<uint32_t*>(&h);
}

// ---------------- kernel ----------------
extern "C" __global__ void __launch_bounds__(THREADS, 1)
STAR_moe_mlp_kernel(
    const float* __restrict__ obs,
    const float* __restrict__ W1b, const float* __restrict__ b1b,
    const float* __restrict__ W2b, const float* __restrict__ b2b,
    const float* __restrict__ W1c, const float* __restrict__ b1c,
    const float* __restrict__ W2c, const float* __restrict__ b2c,
    const float* __restrict__ W1p, const float* __restrict__ b1p,
    const float* __restrict__ W2p, const float* __restrict__ b2p,
    float* __restrict__ out)
{
    extern __shared__ char smem_raw[];
    uint32_t sb0 = s2u(smem_raw);
    uint32_t sb  = (sb0 + 1023u) & ~1023u;
    char* smb = smem_raw + (sb - sb0);

    const int tid = threadIdx.x;
    const int wid = tid >> 5, l = tid & 31;

    int*   perm  = reinterpret_cast<int*>(smb + SM_PERM);
    int*   cnts  = reinterpret_cast<int*>(smb + SM_CNT);
    float* b1cat = reinterpret_cast<float*>(smb + SM_B1CAT);
    float* b2s   = reinterpret_cast<float*>(smb + SM_B2S);

    // ---- one-time setup: fused weights (fp16) + biases into SMEM ----
    for (int idx = tid; idx < 64 * 256; idx += THREADS) {       // B1: [k=64][n=256] (b|c)
        int k = idx >> 8, n = idx & 255;
        float w = (n < 128) ? W1b[k * 128 + n] * W1p[k * 128 + n]
                            : W1c[k * 128 + (n - 128)] * W1p[k * 128 + (n - 128)];
        *reinterpret_cast<__half*>(smb + SM_B1 + (uint32_t)(k * LD1 + n) * 2) = __float2half_rn(w);
    }
    for (int idx = tid; idx < 256 * 64; idx += THREADS) {       // B2: [k=256][n=64] (b|c in k)
        int k = idx >> 6, n = idx & 63;
        float w = (k < 128) ? W2b[k * 64 + n] * W2p[k * 64 + n]
                            : W2c[(k - 128) * 64 + n] * W2p[(k - 128) * 64 + n];
        *reinterpret_cast<__half*>(smb + SM_B2 + (uint32_t)(k * LD2 + n) * 2) = __float2half_rn(w);
    }
    for (int i = tid; i < 256; i += THREADS)
        b1cat[i] = (i < 128) ? b1b[i] + b1p[i] : b1c[i - 128] + b1p[i - 128];
    for (int i = tid; i < 128; i += THREADS)
        b2s[i] = (i < 64) ? b2b[i] + b2p[i] : b2c[i - 64] + b2p[i - 64];
    if (tid < 4) cnts[tid] = 0;

    // ---- prologue: async-load first obs tile (tiles < 148 are fully valid) ----
    {
        const float4* g = reinterpret_cast<const float4*>(obs + (size_t)blockIdx.x * (TILE_M * 64));
        #pragma unroll
        for (int i = 0; i < 8; i++) {
            int f = i * THREADS + tid;
            if (f < TILE_F4) cp16(sb + SM_XS + (uint32_t)f * 16, g + f);
        }
    }
    CP_COMMIT();

    for (int it = 0;; it++) {
        int tile = blockIdx.x + it * GRID_CTAS;
        if (tile >= NTILES) break;
        const int par = it & 1;
        int* cb = cnts + par * 2;

        CP_WAIT0();
        __syncthreads();                       // XS ready; prev compute (A1/perm reads) done

        // final partial tile: stale perm entries would corrupt scatter — re-init
        if (tile == NTILES - 1) {
            if (tid < TILE_M) perm[tid] = -1;
            __syncthreads();
        }

        // ---- phase A (single phase): counters-reset + perm atomics + streaming convert ----
        if (tid == 0) { cnts[(par ^ 1) * 2] = 0; cnts[(par ^ 1) * 2 + 1] = 0; }
        if (tid < TILE_M) {
            if (tile * TILE_M + tid < NROWS) {
                float2 v = *reinterpret_cast<const float2*>(smb + SM_XS + tid * 256 + 8);
                bool isb = (v.x == 1.0f && v.y == 0.0f);
                int pos = isb ? atomicAdd(&cb[0], 1)
                              : (TILE_M - 1) - atomicAdd(&cb[1], 1);
                perm[pos] = (tid << 1) | (isb ? 1 : 0);
            }
        }
        {   // streaming fp32 -> fp16, row order unchanged (no gather)
            const float4* xs4 = reinterpret_cast<const float4*>(smb + SM_XS);
            #pragma unroll
            for (int i = 0; i < 8; i++) {
                int f = i * THREADS + tid;
                if (f < TILE_F4) {
                    int row = f >> 4, c4 = f & 15;
                    float4 x = xs4[f];
                    uint2 pp;
                    pp.x = packh2(x.x, x.y);
                    pp.y = packh2(x.z, x.w);
                    *reinterpret_cast<uint2*>(smb + SM_A1 + (uint32_t)(row * (LDA * 2) + c4 * 8)) = pp;
                }
            }
        }
        __syncthreads();

        // ---- prefetch next tile (XS now free; overlaps compute) ----
        int nt = tile + GRID_CTAS;
        if (nt < NTILES) {
            const float4* g = reinterpret_cast<const float4*>(obs + (size_t)nt * (TILE_M * 64));
            int lim = NF4 - nt * TILE_F4;
            if (lim > TILE_F4) lim = TILE_F4;
            #pragma unroll
            for (int i = 0; i < 8; i++) {
                int f = i * THREADS + tid;
                if (f < lim) cp16(sb + SM_XS + (uint32_t)f * 16, g + f);
            }
        }
        CP_COMMIT();

        // ---- slot assignment: one 16-row single-expert slot per warp ----
        int cnt_b = cb[0], cnt_c = cb[1];
        int cstart = TILE_M - cnt_c;
        int sb_slots = (cnt_b + 15) >> 4;
        int slot, e;
        bool active;
        if (wid < sb_slots) { slot = wid; e = 1; active = true; }
        else { slot = (cstart >> 4) + (wid - sb_slots); e = 0; active = (slot <= 18); }

        if (active) {
            // expert half: b (e=1) at hidden cols [0,128), c (e=0) at [128,256)
            const int ebase = e ? 0 : 128;

            // ---- A fragments via ldmatrix ROW-GATHER through perm ----
            int pv = perm[slot * 16 + (l & 15)];
            int grow = (pv >= 0) ? (pv >> 1) : 0;
            uint32_t abase = sb + SM_A1 + (uint32_t)grow * (LDA * 2) + (uint32_t)((l >> 4) * 16);
            uint32_t a1f[4][4];
            #pragma unroll
            for (int kb = 0; kb < 4; kb++)
                ldsm_x4(a1f[kb], abase + kb * 32);

            float acc2[8][4];
            #pragma unroll
            for (int nbt = 0; nbt < 8; nbt++)
                #pragma unroll
                for (int q = 0; q < 4; q++) acc2[nbt][q] = 0.f;

            // ---- interleaved: per n16 hidden group: L1 mma -> relu -> L2 mma ----
            #pragma unroll
            for (int c = 0; c < 2; c++) {
                int hbase = ebase + c * 64;
                #pragma unroll
                for (int p = 0; p < 4; p++) {
                    float acc1[2][4];
                    #pragma unroll
                    for (int j = 0; j < 2; j++)
                        #pragma unroll
                        for (int q = 0; q < 4; q++) acc1[j][q] = 0.f;

                    #pragma unroll
                    for (int kb = 0; kb < 4; kb++) {
                        uint32_t b[4];
                        ldsm_x4t(b, sb + SM_B1 + (uint32_t)((kb * 16 + (l & 15)) * LD1
                                                            + hbase + p * 16 + (l >> 4) * 8) * 2);
                        mma16816(acc1[0], a1f[kb], b[0], b[1]);
                        mma16816(acc1[1], a1f[kb], b[2], b[3]);
                    }

                    // bias + relu -> fp16 L2-A fragment for this k16 group
                    uint32_t a2[4];
                    #pragma unroll
                    for (int j = 0; j < 2; j++) {
                        int colb = hbase + p * 16 + j * 8 + 2 * (l & 3);
                        float2 bi = *reinterpret_cast<const float2*>(b1cat + colb);
                        float v0 = fmaxf(acc1[j][0] + bi.x, 0.f);
                        float v1 = fmaxf(acc1[j][1] + bi.y, 0.f);
                        float v2 = fmaxf(acc1[j][2] + bi.x, 0.f);
                        float v3 = fmaxf(acc1[j][3] + bi.y, 0.f);
                        a2[j * 2 + 0] = packh2(v0, v1);
                        a2[j * 2 + 1] = packh2(v2, v3);
                    }

                    // L2 partial accumulation for this k16 group
                    #pragma unroll
                    for (int p2 = 0; p2 < 4; p2++) {
                        uint32_t b[4];
                        ldsm_x4t(b, sb + SM_B2 + (uint32_t)((hbase + p * 16 + (l & 15)) * LD2
                                                            + p2 * 16 + (l >> 4) * 8) * 2);
                        mma16816(acc2[2 * p2],     a2, b[0], b[1]);
                        mma16816(acc2[2 * p2 + 1], a2, b[2], b[3]);
                    }
                }
            }

            // ---- store: routed bias, scatter by perm, gate overlap/invalid rows ----
            const float* bb = b2s + (e ? 0 : 64);
            int p0 = slot * 16 + (l >> 2), p1 = p0 + 8;
            int v0 = perm[p0], v1 = perm[p1];
            bool s0 = (v0 >= 0) && ((v0 & 1) == e);
            bool s1 = (v1 >= 0) && ((v1 & 1) == e);
            size_t base = (size_t)tile * TILE_M;
            float* o0 = out + (base + (size_t)(v0 >> 1)) * 64;
            float* o1 = out + (base + (size_t)(v1 >> 1)) * 64;
            #pragma unroll
            for (int nbt = 0; nbt < 8; nbt++) {
                int cb2 = nbt * 8 + (l & 3) * 2;
                if (s0) {
                    float2 o; o.x = acc2[nbt][0] + bb[cb2]; o.y = acc2[nbt][1] + bb[cb2 + 1];
                    *reinterpret_cast<float2*>(o0 + cb2) = o;
                }
                if (s1) {
                    float2 o; o.x = acc2[nbt][2] + bb[cb2]; o.y = acc2[nbt][3] + bb[cb2 + 1];
                    *reinterpret_cast<float2*>(o1 + cb2) = o;
                }
            }
        }
    }
}

// ---------------- launch ----------------
extern "C" void kernel_launch(void* const* d_in, const int* in_sizes, int n_in,
                              void* d_out, int out_size) {
    (void)in_sizes; (void)n_in; (void)out_size;
    cudaFuncSetAttribute(STAR_moe_mlp_kernel,
                         cudaFuncAttributeMaxDynamicSharedMemorySize, SMEM_BYTES);
    STAR_moe_mlp_kernel<<<GRID_CTAS, THREADS, SMEM_BYTES>>>(
        (const float*)d_in[0],
        (const float*)d_in[1],  (const float*)d_in[2],
        (const float*)d_in[3],  (const float*)d_in[4],
        (const float*)d_in[5],  (const float*)d_in[6],
        (const float*)d_in[7],  (const float*)d_in[8],
        (const float*)d_in[9],  (const float*)d_in[10],
        (const float*)d_in[11], (const float*)d_in[12],
        (float*)d_out);
}